// round 17
// baseline (speedup 1.0000x reference)
#include <cuda_runtime.h>

// Fused 6-layer ReLU RNN + FC + log_softmax, diagonal-wavefront persistent kernel.
// R17: k-packed f32x2 (h rows stored as (h_k,h_k+1) pairs -> weights naturally
//      paired, NO dup2, half the weight registers). Role-split pipeline with
//      R14's validated 2-tick layer skew. grid=296=148x2 -> exactly 2 CTAs on
//      every SM (perfect balance, all 148 SMs), 7 batch elems per CTA.
//      NTH=288: 240 layer lanes (2 roles x 2 batch-groups x 6L x 10 neuron-duo),
//      1 aux warp (x loaders + fused fc/softmax). ~75 regs, no spill.

#define TT 1024
#define BB 2048
#define HH 20
#define LL 6
#define ROWS 7         // row 0 = x, row l+1 = h_l
#define NBC 7          // batch elements per CTA
#define NBPAD 8
#define HSTR 12        // u64 stride per batch row (10 used + pad, 16B-aligned)
#define SSTR 24        // f32 stride per batch in wi-stage (20 used + pad)
#define NTH 288
#define NCTA 296
#define NTICK (TT + 12)

typedef unsigned long long u64;

__device__ __forceinline__ u64 f2fma(u64 a, u64 b, u64 c) {
    u64 r; asm("fma.rn.f32x2 %0, %1, %2, %3;" : "=l"(r) : "l"(a), "l"(b), "l"(c)); return r;
}
__device__ __forceinline__ u64 pk2(float lo, float hi) {
    u64 r; asm("mov.b64 %0, {%1, %2};" : "=l"(r) : "f"(lo), "f"(hi)); return r;
}
__device__ __forceinline__ void unpk(u64 a, float& lo, float& hi) {
    asm("mov.b64 {%0, %1}, %2;" : "=f"(lo), "=f"(hi) : "l"(a));
}

// k-packed 20-input dot -> scalar. w[q] = (w_2q, w_2q+1); h regs preloaded.
__device__ __forceinline__ float dot10(const u64 (&w)[10], const u64 (&h)[10], float init) {
    u64 a0 = pk2(init, 0.0f), a1 = 0ull;
#pragma unroll
    for (int q = 0; q < 5; q++) {
        a0 = f2fma(w[2 * q],     h[2 * q],     a0);
        a1 = f2fma(w[2 * q + 1], h[2 * q + 1], a1);
    }
    float l0, h0, l1, h1;
    unpk(a0, l0, h0); unpk(a1, l1, h1);
    return (l0 + h0) + (l1 + h1);
}
__device__ __forceinline__ void loadrow(u64 (&h)[10], const u64* base) {
    const ulonglong2* v = (const ulonglong2*)base;
#pragma unroll
    for (int q = 0; q < 5; q++) { ulonglong2 t = v[q]; h[2 * q] = t.x; h[2 * q + 1] = t.y; }
}

__global__ __launch_bounds__(NTH, 2) void rnn_wavefront_kernel(
    const float* __restrict__ x,     // [T, B, 2]
    const float* __restrict__ Wih0,  // [H, 2]
    const float* __restrict__ Wih,   // [L-1, H, H]
    const float* __restrict__ Whh,   // [L, H, H]
    const float* __restrict__ bih,   // [L, H]
    const float* __restrict__ bhh,   // [L, H]
    const float* __restrict__ fcw,   // [2, H]
    const float* __restrict__ fcb,   // [2]
    float* __restrict__ out)         // [T, B, 2]
{
    __shared__ __align__(16) u64   hb[2][ROWS][NBPAD * HSTR];  // x + h, double-buffered
    __shared__ __align__(16) float st[2][LL][NBPAD * SSTR];    // staged wi scalars

    const int tid = threadIdx.x;

    for (int i = tid; i < 2 * ROWS * NBPAD * HSTR; i += NTH) ((u64*)hb)[i] = 0ull;
    for (int i = tid; i < 2 * LL * NBPAD * SSTR; i += NTH)   ((float*)st)[i] = 0.0f;

    // ---- decomposition ----
    // layer lanes: tid<256: block = tid/64: role = block>>1 (0=wi, 1=wh), bg = block&1
    //              sub = tid%64 (<60 active): l = sub/10, jd = sub%10 (duo jd, jd+10)
    const int blk  = tid >> 6;
    const int sub  = tid & 63;
    const bool is_layer = (tid < 256) && (sub < 60);
    const int role = blk >> 1;
    const int bg   = blk & 1;
    const int l    = sub / 10;
    const int jd   = sub % 10;
    const int bbase = bg * 4;
    const int nb    = bg ? 3 : 4;        // batches 0-3 / 4-6

    const int alane = tid - 256;                       // aux warp
    const bool is_xl = (tid >= 256) && (alane < NBC);  // x loader, batch=alane
    const bool is_fc = (tid >= 256) && (alane >= 8) && (alane < 8 + NBC); // fc/softmax
    const int fcb_i  = alane - 8;                      // batch for fc lane

    // ---- weights into registers (k-packed: float2 -> u64, no duplication) ----
    u64 wA[10], wB[10];
    float bA = 0.0f, bB = 0.0f;
#pragma unroll
    for (int q = 0; q < 10; q++) { wA[q] = 0ull; wB[q] = 0ull; }

    if (is_layer) {
        if (role == 1) {          // wh: recurrent rows jd, jd+10
#pragma unroll
            for (int q = 0; q < 10; q++) {
                float2 a = *(const float2*)&Whh[(l * HH + jd) * HH + 2 * q];
                float2 b = *(const float2*)&Whh[(l * HH + jd + 10) * HH + 2 * q];
                wA[q] = pk2(a.x, a.y); wB[q] = pk2(b.x, b.y);
            }
        } else if (l > 0) {       // wi rows
#pragma unroll
            for (int q = 0; q < 10; q++) {
                float2 a = *(const float2*)&Wih[((l - 1) * HH + jd) * HH + 2 * q];
                float2 b = *(const float2*)&Wih[((l - 1) * HH + jd + 10) * HH + 2 * q];
                wA[q] = pk2(a.x, a.y); wB[q] = pk2(b.x, b.y);
            }
            bA = bih[l * HH + jd] + bhh[l * HH + jd];
            bB = bih[l * HH + jd + 10] + bhh[l * HH + jd + 10];
        } else {                  // layer 0: x-projection in slot 0 only
            float2 a = *(const float2*)&Wih0[jd * 2];
            float2 b = *(const float2*)&Wih0[(jd + 10) * 2];
            wA[0] = pk2(a.x, a.y); wB[0] = pk2(b.x, b.y);
            bA = bih[jd] + bhh[jd];
            bB = bih[jd + 10] + bhh[jd + 10];
        }
    } else if (is_fc) {
#pragma unroll
        for (int q = 0; q < 10; q++) {
            float2 a = *(const float2*)&fcw[2 * q];            // class 0
            float2 b = *(const float2*)&fcw[HH + 2 * q];       // class 1
            wA[q] = pk2(a.x, a.y); wB[q] = pk2(b.x, b.y);
        }
        bA = fcb[0]; bB = fcb[1];
    }

    // ---- x prefetch (contiguous float2 per batch; 2-tick reg pipeline) ----
    const float2* __restrict__ x2 = (const float2*)x;   // x2[t*BB + b]
    int gb = 0;
    float xv0 = 0.0f, xv1 = 0.0f;
    if (is_xl) {
        gb = blockIdx.x * NBC + alane;
        if (gb < BB) {
            float2 v0 = x2[gb];                      // x(0)
            ((u64*)&hb[0][0][alane * HSTR])[0] = pk2(v0.x, v0.y);
            float2 v1 = x2[BB + gb];                 // x(1)
            xv0 = v1.x; xv1 = v1.y;
        }
    }
    if (is_fc) gb = blockIdx.x * NBC + fcb_i;

    __syncthreads();

    for (int tau = 0; tau < NTICK; ++tau) {
        const int A = tau & 1;
        const u64(*rb)[NBPAD * HSTR] = hb[A];        // read buffer (last tick)
        u64(*wb)[NBPAD * HSTR] = hb[A ^ 1];          // write buffer (this tick)
        const float(*sr)[NBPAD * SSTR] = st[A];      // staged wi (last tick)
        float(*sw)[NBPAD * SSTR] = st[A ^ 1];        // staged wi (this tick)

        if (is_layer) {
            if (role == 0) {
                // wi(t1) = Wih_l . h_{l-1}(t1) + b,  t1 = tau - 2l
                if ((unsigned)(tau - 2 * l) < TT) {
#pragma unroll
                    for (int b = 0; b < 4; b++) {
                        if (b >= nb) break;
                        const int bb = bbase + b;
                        u64 h[10]; loadrow(h, &rb[l][bb * HSTR]);
                        sw[l][bb * SSTR + jd]      = dot10(wA, h, bA);
                        sw[l][bb * SSTR + jd + 10] = dot10(wB, h, bB);
                    }
                }
            } else {
                // h_l(t0) = relu(Whh_l . h_l(t0-1) + wi(t0)),  t0 = tau - 2l - 1
                if ((unsigned)(tau - 2 * l - 1) < TT) {
#pragma unroll
                    for (int b = 0; b < 4; b++) {
                        if (b >= nb) break;
                        const int bb = bbase + b;
                        u64 h[10]; loadrow(h, &rb[l + 1][bb * HSTR]);
                        float rA = dot10(wA, h, sr[l][bb * SSTR + jd]);
                        float rB = dot10(wB, h, sr[l][bb * SSTR + jd + 10]);
                        float* hw = (float*)&wb[l + 1][bb * HSTR];
                        hw[jd]      = fmaxf(rA, 0.0f);
                        hw[jd + 10] = fmaxf(rB, 0.0f);
                    }
                }
            }
        } else if (is_xl) {
            // stage x(tau+1) from regs; prefetch x(tau+2)
            if (tau + 1 < TT) {
                ((u64*)&wb[0][alane * HSTR])[0] = pk2(xv0, xv1);
            }
            if (tau + 2 < TT && gb < BB) {
                float2 v = x2[(tau + 2) * BB + gb];
                xv0 = v.x; xv1 = v.y;
            }
        } else if (is_fc) {
            // fc + log_softmax + store, t = tau - 12 (h_5 written last tick)
            if ((unsigned)(tau - 12) < TT && gb < BB) {
                const int t = tau - 12;
                u64 h[10]; loadrow(h, &rb[LL][fcb_i * HSTR]);
                float u0 = dot10(wA, h, bA);
                float u1 = dot10(wB, h, bB);
                float m = fmaxf(u0, u1);
                float lse = m + __logf(1.0f + __expf(fminf(u0, u1) - m));
                *(float2*)&out[(size_t)(t * BB + gb) * 2] = make_float2(u0 - lse, u1 - lse);
            }
        }

        __syncthreads();
    }
}

extern "C" void kernel_launch(void* const* d_in, const int* in_sizes, int n_in,
                              void* d_out, int out_size) {
    const float* x    = (const float*)d_in[0];
    const float* Wih0 = (const float*)d_in[1];
    const float* Wih  = (const float*)d_in[2];
    const float* Whh  = (const float*)d_in[3];
    const float* bih  = (const float*)d_in[4];
    const float* bhh  = (const float*)d_in[5];
    const float* fcw  = (const float*)d_in[6];
    const float* fcb  = (const float*)d_in[7];
    float* out = (float*)d_out;

    rnn_wavefront_kernel<<<NCTA, NTH>>>(x, Wih0, Wih, Whh, bih, bhh, fcw, fcb, out);
}